// round 1
// baseline (speedup 1.0000x reference)
#include <cuda_runtime.h>
#include <math.h>

#define BATCH 256
#define SIGLEN 2048
#define L1P 1022     // after conv1(k3)+pool(3,2)
#define L2P 339      // after conv2(k5)+pool(3,3)
#define L3P 168      // after conv3(k3)+pool(3,2)
#define C1 128
#define C2 64
#define C3 64
#define FCIN 10752   // 64*168
#define EPS_BN 1e-5f

// ---- scratch (device globals: allocation-free) ----
__device__ float g_h1[BATCH * C1 * L1P];   // 134 MB
__device__ float g_h2[BATCH * C2 * L2P];   // 22 MB
__device__ float g_h3[BATCH * C3 * L3P];   // 11 MB
__device__ float g_theta[BATCH * 5];

// ============================================================
// Kernel 1: conv1 (3->128, k3, VALID) + BN + maxpool(3,2) + relu
// grid (16, 256), block 128 (one thread per oc)
// ============================================================
__global__ void k_conv1(const float* __restrict__ x,
                        const float* __restrict__ w,
                        const float* __restrict__ bias,
                        const float* __restrict__ bng,
                        const float* __restrict__ bnb,
                        const float* __restrict__ bnm,
                        const float* __restrict__ bnv) {
    const int b  = blockIdx.y;
    const int p0 = blockIdx.x * 64;
    const int oc = threadIdx.x;
    __shared__ float xs[3][132];   // 131 used

    const int t0 = 2 * p0;
    for (int idx = threadIdx.x; idx < 3 * 131; idx += 128) {
        int ch = idx / 131, j = idx % 131;
        int t = t0 + j;
        xs[ch][j] = (t < SIGLEN) ? x[(b * 3 + ch) * SIGLEN + t] : 0.f;
    }
    float wr[9];
#pragma unroll
    for (int j = 0; j < 9; ++j) wr[j] = w[oc * 9 + j];
    float scale = bng[oc] / sqrtf(bnv[oc] + EPS_BN);
    float shift = bnb[oc] + (bias[oc] - bnm[oc]) * scale;
    __syncthreads();

    for (int pl = 0; pl < 64; ++pl) {
        int p = p0 + pl;
        if (p >= L1P) break;
        float c0 = 0.f, c1 = 0.f, c2 = 0.f;
        int base = 2 * pl;
#pragma unroll
        for (int ch = 0; ch < 3; ++ch)
#pragma unroll
            for (int k = 0; k < 3; ++k) {
                float wv = wr[ch * 3 + k];
                c0 = fmaf(wv, xs[ch][base + k], c0);
                c1 = fmaf(wv, xs[ch][base + 1 + k], c1);
                c2 = fmaf(wv, xs[ch][base + 2 + k], c2);
            }
        float y0 = fmaf(c0, scale, shift);
        float y1 = fmaf(c1, scale, shift);
        float y2 = fmaf(c2, scale, shift);
        float y = fmaxf(fmaxf(y0, y1), y2);
        g_h1[(b * C1 + oc) * L1P + p] = fmaxf(y, 0.f);
    }
}

// ============================================================
// Kernel 2: conv2 (128->64, k5) + BN + maxpool(3,3) + relu   [HOT]
// grid (11, 256), block 256: oc = tid&63, t-group = tid>>6
// tile: 32 pooled = 96 conv positions = 100 input positions
// ic chunked by 16 through smem
// ============================================================
__global__ void k_conv2(const float* __restrict__ w,
                        const float* __restrict__ bias,
                        const float* __restrict__ bng,
                        const float* __restrict__ bnb,
                        const float* __restrict__ bnm,
                        const float* __restrict__ bnv) {
    const int b   = blockIdx.y;
    const int p0  = blockIdx.x * 32;
    const int tid = threadIdx.x;
    const int oc  = tid & 63;
    const int gg  = tid >> 6;         // 0..3, 24 conv positions each
    const int tbase = 3 * p0;

    __shared__ float xs[16][100];
    __shared__ float ws[16 * 5 * 64];

    float acc[24];
#pragma unroll
    for (int t = 0; t < 24; ++t) acc[t] = 0.f;

    for (int chunk = 0; chunk < 8; ++chunk) {
        __syncthreads();
        const int ic0 = chunk * 16;
        for (int idx = tid; idx < 16 * 100; idx += 256) {
            int ic = idx / 100, j = idx % 100;
            int t = tbase + j;
            xs[ic][j] = (t < L1P) ? g_h1[(b * C1 + ic0 + ic) * L1P + t] : 0.f;
        }
        for (int idx = tid; idx < 16 * 5 * 64; idx += 256) {
            int o = idx / 80, r = idx % 80;     // coalesced over global runs
            int ic = r / 5, k = r % 5;
            ws[(ic * 5 + k) * 64 + o] = w[o * 640 + (ic0 + ic) * 5 + k];
        }
        __syncthreads();
#pragma unroll 1
        for (int ic = 0; ic < 16; ++ic) {
            float xr[28];
#pragma unroll
            for (int j = 0; j < 28; ++j) xr[j] = xs[ic][gg * 24 + j];
            float wv[5];
#pragma unroll
            for (int k = 0; k < 5; ++k) wv[k] = ws[(ic * 5 + k) * 64 + oc];
#pragma unroll
            for (int t = 0; t < 24; ++t)
#pragma unroll
                for (int k = 0; k < 5; ++k)
                    acc[t] = fmaf(wv[k], xr[t + k], acc[t]);
        }
    }

    float scale = bng[oc] / sqrtf(bnv[oc] + EPS_BN);
    float shift = bnb[oc] + (bias[oc] - bnm[oc]) * scale;
#pragma unroll
    for (int j = 0; j < 8; ++j) {
        int p = p0 + gg * 8 + j;
        if (p < L2P) {
            float y0 = fmaf(acc[3 * j],     scale, shift);
            float y1 = fmaf(acc[3 * j + 1], scale, shift);
            float y2 = fmaf(acc[3 * j + 2], scale, shift);
            g_h2[(b * C2 + oc) * L2P + p] = fmaxf(fmaxf(fmaxf(y0, y1), y2), 0.f);
        }
    }
}

// ============================================================
// Kernel 3: conv3 (64->64, k3) + BN + maxpool(3,2) + relu
// grid (7, 256), block 256: oc = tid&63, group = tid>>6 (6 pooled each)
// tile: 24 pooled = 49 conv positions = 51 input positions
// ============================================================
__global__ void k_conv3(const float* __restrict__ w,
                        const float* __restrict__ bias,
                        const float* __restrict__ bng,
                        const float* __restrict__ bnb,
                        const float* __restrict__ bnm,
                        const float* __restrict__ bnv) {
    const int b   = blockIdx.y;
    const int p0  = blockIdx.x * 24;
    const int tid = threadIdx.x;
    const int oc  = tid & 63;
    const int gg  = tid >> 6;       // conv locals gg*12 .. gg*12+12
    const int tbase = 2 * p0;

    __shared__ float xs[32][52];    // 51 used
    __shared__ float ws[32 * 3 * 64];

    float acc[13];
#pragma unroll
    for (int t = 0; t < 13; ++t) acc[t] = 0.f;

    for (int chunk = 0; chunk < 2; ++chunk) {
        __syncthreads();
        const int ic0 = chunk * 32;
        for (int idx = tid; idx < 32 * 51; idx += 256) {
            int ic = idx / 51, j = idx % 51;
            int t = tbase + j;
            xs[ic][j] = (t < L2P) ? g_h2[(b * C2 + ic0 + ic) * L2P + t] : 0.f;
        }
        for (int idx = tid; idx < 32 * 3 * 64; idx += 256) {
            int o = idx / 96, r = idx % 96;
            int ic = r / 3, k = r % 3;
            ws[(ic * 3 + k) * 64 + o] = w[o * 192 + (ic0 + ic) * 3 + k];
        }
        __syncthreads();
#pragma unroll 1
        for (int ic = 0; ic < 32; ++ic) {
            float xr[15];
#pragma unroll
            for (int j = 0; j < 15; ++j) xr[j] = xs[ic][gg * 12 + j];
            float wv[3];
#pragma unroll
            for (int k = 0; k < 3; ++k) wv[k] = ws[(ic * 3 + k) * 64 + oc];
#pragma unroll
            for (int t = 0; t < 13; ++t)
#pragma unroll
                for (int k = 0; k < 3; ++k)
                    acc[t] = fmaf(wv[k], xr[t + k], acc[t]);
        }
    }

    float scale = bng[oc] / sqrtf(bnv[oc] + EPS_BN);
    float shift = bnb[oc] + (bias[oc] - bnm[oc]) * scale;
#pragma unroll
    for (int j = 0; j < 6; ++j) {
        int p = p0 + gg * 6 + j;
        if (p < L3P) {
            float y0 = fmaf(acc[2 * j],     scale, shift);
            float y1 = fmaf(acc[2 * j + 1], scale, shift);
            float y2 = fmaf(acc[2 * j + 2], scale, shift);
            g_h3[(b * C3 + oc) * L3P + p] = fmaxf(fmaxf(fmaxf(y0, y1), y2), 0.f);
        }
    }
}

// ============================================================
// Kernel 4: fc1(10752->48)+relu, fc2(48->32)+relu, fc3(32->16)+relu,
//           fc4(16->5)+tanh -> theta.  One block per batch row.
// ============================================================
__global__ void k_fc(const float* __restrict__ fc1w, const float* __restrict__ fc1b,
                     const float* __restrict__ fc2w, const float* __restrict__ fc2b,
                     const float* __restrict__ fc3w, const float* __restrict__ fc3b,
                     const float* __restrict__ fc4w, const float* __restrict__ fc4b) {
    const int b   = blockIdx.x;
    const int tid = threadIdx.x;
    __shared__ float row[FCIN];
    __shared__ float s1[48], s2[32], s3[16];

    for (int i = tid; i < FCIN; i += 256) row[i] = g_h3[b * FCIN + i];
    __syncthreads();

    const int warp = tid >> 5, lane = tid & 31;
#pragma unroll 1
    for (int oi = 0; oi < 6; ++oi) {
        int o = warp + 8 * oi;
        float a = 0.f;
        for (int k = lane; k < FCIN; k += 32)
            a = fmaf(row[k], fc1w[o * FCIN + k], a);
#pragma unroll
        for (int off = 16; off > 0; off >>= 1)
            a += __shfl_down_sync(0xffffffffu, a, off);
        if (lane == 0) s1[o] = fmaxf(a + fc1b[o], 0.f);
    }
    __syncthreads();

    if (tid < 32) {
        float a2 = 0.f;
        for (int k = 0; k < 48; ++k) a2 = fmaf(s1[k], fc2w[tid * 48 + k], a2);
        s2[tid] = fmaxf(a2 + fc2b[tid], 0.f);
        __syncwarp();
        if (tid < 16) {
            float a3 = 0.f;
            for (int k = 0; k < 32; ++k) a3 = fmaf(s2[k], fc3w[tid * 32 + k], a3);
            s3[tid] = fmaxf(a3 + fc3b[tid], 0.f);
        }
        __syncwarp();
        if (tid < 5) {
            float a4 = 0.f;
            for (int k = 0; k < 16; ++k) a4 = fmaf(s3[k], fc4w[tid * 16 + k], a4);
            g_theta[b * 5 + tid] = tanhf(a4 + fc4b[tid]);
        }
    }
}

// ============================================================
// Kernel 5: CPAB A = theta @ basis^T, exact flow integration (7 iters),
//           linear resample of x along time. One block per batch.
// ============================================================
__global__ void k_warp(const float* __restrict__ x,
                       const float* __restrict__ basis,
                       float* __restrict__ out) {
    const int b   = blockIdx.x;
    const int tid = threadIdx.x;
    __shared__ float sa[6], sb[6];
    if (tid < 12) {
        float a = 0.f;
#pragma unroll
        for (int k = 0; k < 5; ++k)
            a = fmaf(g_theta[b * 5 + k], basis[tid * 5 + k], a);
        if (tid & 1) sb[tid >> 1] = a; else sa[tid >> 1] = a;
    }
    __syncthreads();
    float la[6], lb[6];
#pragma unroll
    for (int c = 0; c < 6; ++c) { la[c] = sa[c]; lb[c] = sb[c]; }
    const float INF = __int_as_float(0x7f800000);

    for (int r = 0; r < 8; ++r) {
        int i = tid + r * 256;
        float xv = (float)i / 2047.0f;
        float t = 1.0f;
#pragma unroll 1
        for (int it = 0; it < 7; ++it) {     // NC+1 iterations
            int c = (int)floorf(xv * 6.0f);
            c = c < 0 ? 0 : (c > 5 ? 5 : c);
            float a  = la[c];
            float bc = lb[c];
            float v  = fmaf(a, xv, bc);
            float xb = (v >= 0.f) ? (float)(c + 1) / 6.0f : (float)c / 6.0f;
            bool  big = fabsf(a) > 1e-8f;
            float a_s = big ? a : 1.0f;
            float boa = bc / a_s;
            float z   = xv + boa;
            float zb  = xb + boa;
            float zden  = (fabsf(z) > 1e-12f) ? z : 1e-12f;
            float ratio = zb / zden;
            float t_exp = logf(fmaxf(ratio, 1e-12f)) / a_s;
            float v_s   = (fabsf(v) > 1e-12f) ? v : 1.0f;
            float t_lin = (xb - xv) / v_s;
            float thit  = big ? t_exp : t_lin;
            bool valid = (fabsf(v) > 1e-12f) && (thit > 0.f) &&
                         ((big ? ratio : 1.0f) > 0.f);
            thit = valid ? thit : INF;
            float tau = fminf(t, thit);
            float x_new = big ? (z * expf(a * tau) - (z - xv))
                              : fmaf(bc, tau, xv);
            bool hit = (thit <= t);
            float nudge = (v >= 0.f) ? 1e-6f : -1e-6f;
            xv = hit ? (xb + nudge) : x_new;
            xv = fminf(fmaxf(xv, 0.f), 1.f);
            t = fmaxf(t - tau, 0.f);
        }
        // linear interp of x (per channel) at position xv
        float p = fminf(fmaxf(xv, 0.f), 1.f) * 2047.0f;
        int x0 = (int)floorf(p);
        x0 = x0 < 0 ? 0 : (x0 > 2046 ? 2046 : x0);
        float wgt = p - (float)x0;
#pragma unroll
        for (int ch = 0; ch < 3; ++ch) {
            float d0 = x[(b * 3 + ch) * SIGLEN + x0];
            float d1 = x[(b * 3 + ch) * SIGLEN + x0 + 1];
            out[(b * 3 + ch) * SIGLEN + i] = d0 * (1.0f - wgt) + d1 * wgt;
        }
    }
}

// ============================================================
extern "C" void kernel_launch(void* const* d_in, const int* in_sizes, int n_in,
                              void* d_out, int out_size) {
    const float* x       = (const float*)d_in[0];
    const float* c1w     = (const float*)d_in[1];
    const float* c1b     = (const float*)d_in[2];
    const float* bn1g    = (const float*)d_in[3];
    const float* bn1b    = (const float*)d_in[4];
    const float* bn1m    = (const float*)d_in[5];
    const float* bn1v    = (const float*)d_in[6];
    const float* c2w     = (const float*)d_in[7];
    const float* c2b     = (const float*)d_in[8];
    const float* bn2g    = (const float*)d_in[9];
    const float* bn2b    = (const float*)d_in[10];
    const float* bn2m    = (const float*)d_in[11];
    const float* bn2v    = (const float*)d_in[12];
    const float* c3w     = (const float*)d_in[13];
    const float* c3b     = (const float*)d_in[14];
    const float* bn3g    = (const float*)d_in[15];
    const float* bn3b    = (const float*)d_in[16];
    const float* bn3m    = (const float*)d_in[17];
    const float* bn3v    = (const float*)d_in[18];
    const float* fc1w    = (const float*)d_in[19];
    const float* fc1b    = (const float*)d_in[20];
    const float* fc2w    = (const float*)d_in[21];
    const float* fc2b    = (const float*)d_in[22];
    const float* fc3w    = (const float*)d_in[23];
    const float* fc3b    = (const float*)d_in[24];
    const float* fc4w    = (const float*)d_in[25];
    const float* fc4b    = (const float*)d_in[26];
    const float* basis   = (const float*)d_in[27];
    float* out = (float*)d_out;

    dim3 g1(16, BATCH);  k_conv1<<<g1, 128>>>(x, c1w, c1b, bn1g, bn1b, bn1m, bn1v);
    dim3 g2(11, BATCH);  k_conv2<<<g2, 256>>>(c2w, c2b, bn2g, bn2b, bn2m, bn2v);
    dim3 g3(7,  BATCH);  k_conv3<<<g3, 256>>>(c3w, c3b, bn3g, bn3b, bn3m, bn3v);
    k_fc<<<BATCH, 256>>>(fc1w, fc1b, fc2w, fc2b, fc3w, fc3b, fc4w, fc4b);
    k_warp<<<BATCH, 256>>>(x, basis, out);
}